// round 9
// baseline (speedup 1.0000x reference)
#include <cuda_runtime.h>
#include <math.h>

#define HDIM 512
#define BSZ  128
#define TIN  256
#define MLEN 128
#define VOC  32
#define BH   (BSZ*HDIM)
#define B2H  (BSZ*2*HDIM)
#define NBLK 148
#define NTHR 512

typedef unsigned long long u64;

// ---------------- device scratch ----------------
__device__ float g_y0[TIN*BH];
__device__ float g_enc[TIN*BH];
__device__ float g_q[MLEN*BH];
__device__ float g_rnn[MLEN*B2H];
__device__ float g_h0[MLEN*BH];
__device__ float g_h1[MLEN*BH];
__device__ unsigned g_arrive;
__device__ volatile unsigned g_release;

// dataflow counters: [step][rowtile], target 32 producers each
__device__ int cY0 [TIN][4];
__device__ int cEnc[TIN][4];
__device__ int cQ  [MLEN][4];
__device__ int cRnn[MLEN][4];
__device__ int cH0 [MLEN][4];
__device__ int cH1 [MLEN][4];

// ---------------- shared memory ----------------
struct SmSlice { float hs[2][32][36]; float ws[2][48][36]; };   // 23040 B
struct SmA { float q[HDIM]; float sc[TIN]; float red[16]; };
struct SmL { float hrow[HDIM]; float lg[VOC]; int best; };
union SmAll {
    SmSlice sl[4];            // 92160 B
    u64 comb[3][128][16];     // 49152 B (used only after GEMMs complete)
    SmA a;
    SmL l;
};

// ---------------- packed f32x2 helpers ----------------
__device__ __forceinline__ u64 fma2(u64 a, u64 b, u64 c)
{
    u64 d;
    asm("fma.rn.f32x2 %0, %1, %2, %3;" : "=l"(d) : "l"(a), "l"(b), "l"(c));
    return d;
}
__device__ __forceinline__ u64 add2(u64 a, u64 b)
{
    u64 d;
    asm("add.rn.f32x2 %0, %1, %2;" : "=l"(d) : "l"(a), "l"(b));
    return d;
}
__device__ __forceinline__ float red2(u64 a)
{
    float lo, hi;
    asm("mov.b64 {%0, %1}, %2;" : "=f"(lo), "=f"(hi) : "l"(a));
    return lo + hi;
}

// named barrier for one 128-thread k-slice (ids 1..4)
__device__ __forceinline__ void barg(int slice)
{
    asm volatile("bar.sync %0, %1;" :: "r"(slice + 1), "r"(128) : "memory");
}

// ---------------- dataflow wait / signal ----------------
__device__ __forceinline__ void waits2(const int* c1, const int* c2)
{
    if (threadIdx.x == 0) {
        if (c1) while (*(volatile const int*)c1 < 32) __nanosleep(64);
        if (c2) while (*(volatile const int*)c2 < 32) __nanosleep(64);
        __threadfence();
    }
    __syncthreads();
}
__device__ __forceinline__ void done(int* c)
{
    __syncthreads();
    if (threadIdx.x == 0) { __threadfence(); atomicAdd(c, 1); }
}

// ---------------- software grid barrier (used twice) ----------------
__device__ __forceinline__ void gsync(unsigned &phase)
{
    __threadfence();
    __syncthreads();
    phase++;
    if (threadIdx.x == 0) {
        unsigned p = phase;
        unsigned old = atomicAdd(&g_arrive, 1u);
        if (old == p * (unsigned)NBLK - 1u) {
            g_release = p;
        } else {
            while (g_release < p) { }
        }
        __threadfence();
    }
    __syncthreads();
}

// ---------------- pipelined K-major GEMM accumulate (per 128-thread k-slice) ----------------
template<int NG>
__device__ __forceinline__ void gemm_pipe(
    const float* __restrict__ A, int lda,
    const float* __restrict__ W, int ldw,
    int kBase, int Kh, int rowBase, int colBase,
    u64 (&a0)[4], u64 (&a1)[4], u64 (&a2)[4],
    SmSlice& sg, int slice)
{
    const int t1  = threadIdx.x & 127;
    const int cL  = t1 & 15;
    const int rG  = t1 >> 4;           // 0..7

    const int ldR = t1 >> 3;           // 0..15
    const int ldK = (t1 & 7) << 2;     // 0,4,...,28

    const size_t hOffA = (size_t)(rowBase + ldR) * lda + kBase + ldK;
    const size_t hOffB = (size_t)(rowBase + 16 + ldR) * lda + kBase + ldK;
    const size_t wOff0 = (size_t)(0*HDIM + colBase + ldR) * ldw + kBase + ldK;
    const size_t wOff1 = (size_t)(1*HDIM + colBase + ldR) * ldw + kBase + ldK;
    const size_t wOff2 = (size_t)(2*HDIM + colBase + ldR) * ldw + kBase + ldK;

    const int nt = Kh >> 5;
    float4 pH0, pH1, pW0, pW1, pW2;

#define GLD(kt) do { int k0_ = (kt) << 5;                               \
        pH0 = *(const float4*)(A + hOffA + k0_);                        \
        pH1 = *(const float4*)(A + hOffB + k0_);                        \
        pW0 = *(const float4*)(W + wOff0 + k0_);                        \
        if (NG >= 2) pW1 = *(const float4*)(W + wOff1 + k0_);           \
        if (NG >= 3) pW2 = *(const float4*)(W + wOff2 + k0_);           \
    } while (0)
#define GST(b) do {                                                     \
        *(float4*)&sg.hs[b][ldR][ldK]      = pH0;                       \
        *(float4*)&sg.hs[b][16+ldR][ldK]   = pH1;                       \
        *(float4*)&sg.ws[b][ldR][ldK]      = pW0;                       \
        if (NG >= 2) *(float4*)&sg.ws[b][16+ldR][ldK] = pW1;            \
        if (NG >= 3) *(float4*)&sg.ws[b][32+ldR][ldK] = pW2;            \
    } while (0)

    GLD(0); GST(0);
    if (nt > 1) GLD(1);
    barg(slice);

    for (int kt = 0; kt < nt; kt++) {
        const int cur = kt & 1;
        if (kt + 1 < nt) GST(cur ^ 1);
        if (kt + 2 < nt) GLD(kt + 2);
        #pragma unroll
        for (int kk = 0; kk < 32; kk += 4) {
            ulonglong2 w0 = *(const ulonglong2*)&sg.ws[cur][cL][kk];
            ulonglong2 w1, w2;
            if (NG >= 2) w1 = *(const ulonglong2*)&sg.ws[cur][16 + cL][kk];
            if (NG >= 3) w2 = *(const ulonglong2*)&sg.ws[cur][32 + cL][kk];
            #pragma unroll
            for (int i = 0; i < 4; i++) {
                ulonglong2 h = *(const ulonglong2*)&sg.hs[cur][rG*4 + i][kk];
                a0[i] = fma2(h.x, w0.x, a0[i]);
                a0[i] = fma2(h.y, w0.y, a0[i]);
                if (NG >= 2) { a1[i] = fma2(h.x, w1.x, a1[i]);
                               a1[i] = fma2(h.y, w1.y, a1[i]); }
                if (NG >= 3) { a2[i] = fma2(h.x, w2.x, a2[i]);
                               a2[i] = fma2(h.y, w2.y, a2[i]); }
            }
        }
        barg(slice);
    }
#undef GLD
#undef GST
}

// ---------------- one GRU output tile: 32 rows x 16 cols (512 threads, 4-way k-split) ----------------
__device__ void gru_tile(const float* __restrict__ h_in,
                         const float* __restrict__ Whh,
                         const float* __restrict__ bhh,
                         const float* __restrict__ xin,
                         int ldx, int KIN,
                         const float* __restrict__ Wih,
                         const float* __restrict__ bih,
                         float* __restrict__ h_out,
                         int rowBase, int colBase, SmAll& sm)
{
    const int tid   = threadIdx.x;
    const int t1    = tid & 127;
    const int slice = tid >> 7;
    const int cL    = t1 & 15;
    const int rG    = t1 >> 4;
    const int col   = colBase + cL;

    u64 ar[4] = {0,0,0,0}, az[4] = {0,0,0,0};
    u64 ahn[4] = {0,0,0,0}, ain[4] = {0,0,0,0};
    float xr[4] = {0.f,0.f,0.f,0.f}, xz[4] = {0.f,0.f,0.f,0.f}, xn[4] = {0.f,0.f,0.f,0.f};

    if (h_in)
        gemm_pipe<3>(h_in, HDIM, Whh, HDIM, slice*(HDIM/4), HDIM/4,
                     rowBase, colBase, ar, az, ahn, sm.sl[slice], slice);

    if (KIN >= 32) {
        const int Kq = KIN / 4;
        gemm_pipe<3>(xin, ldx, Wih, KIN, slice*Kq, Kq,
                     rowBase, colBase, ar, az, ain, sm.sl[slice], slice);
    } else if (slice == 0) {
        for (int k = 0; k < KIN; k++) {
            float wr = Wih[(size_t)(0*HDIM + col)*KIN + k];
            float wz = Wih[(size_t)(1*HDIM + col)*KIN + k];
            float wn = Wih[(size_t)(2*HDIM + col)*KIN + k];
            #pragma unroll
            for (int i = 0; i < 4; i++) {
                float xv = xin[(size_t)(rowBase + rG*4 + i)*ldx + k];
                xr[i] = fmaf(xv, wr, xr[i]);
                xz[i] = fmaf(xv, wz, xz[i]);
                xn[i] = fmaf(xv, wn, xn[i]);
            }
        }
    }

    __syncthreads();
    if (slice) {
        u64* d = sm.comb[slice-1][t1];
        #pragma unroll
        for (int i = 0; i < 4; i++) {
            d[i]      = ar[i];
            d[4 + i]  = az[i];
            d[8 + i]  = ahn[i];
            d[12 + i] = ain[i];
        }
    }
    __syncthreads();
    if (slice == 0) {
        #pragma unroll
        for (int s = 0; s < 3; s++) {
            const u64* d = sm.comb[s][t1];
            #pragma unroll
            for (int i = 0; i < 4; i++) {
                ar[i]  = add2(ar[i],  d[i]);
                az[i]  = add2(az[i],  d[4 + i]);
                ahn[i] = add2(ahn[i], d[8 + i]);
                ain[i] = add2(ain[i], d[12 + i]);
            }
        }

        const float bhr = bhh[col], bhz = bhh[HDIM+col], bhn = bhh[2*HDIM+col];
        const float bir = bih[col], biz = bih[HDIM+col], bin = bih[2*HDIM+col];

        #pragma unroll
        for (int i = 0; i < 4; i++) {
            int row = rowBase + rG*4 + i;
            float accr = red2(ar[i]) + xr[i] + bhr + bir;
            float accz = red2(az[i]) + xz[i] + bhz + biz;
            float hnv  = red2(ahn[i]) + bhn;
            float inv  = red2(ain[i]) + xn[i] + bin;
            float r = 1.f / (1.f + expf(-accr));
            float z = 1.f / (1.f + expf(-accz));
            float n = tanhf(inv + r * hnv);
            float hp = h_in ? h_in[(size_t)row*HDIM + col] : 0.f;
            h_out[(size_t)row*HDIM + col] = (1.f - z) * n + z * hp;
        }
    }
    __syncthreads();
}

// ---------------- linear tile: out = A @ W.T + b (512 threads, 4-way k-split) ----------------
__device__ void linear_tile(const float* __restrict__ A,
                            const float* __restrict__ W,
                            const float* __restrict__ bias,
                            float* __restrict__ out,
                            int rowBase, int colBase, SmAll& sm)
{
    const int tid   = threadIdx.x;
    const int t1    = tid & 127;
    const int slice = tid >> 7;
    const int cL    = t1 & 15;
    const int rG    = t1 >> 4;

    u64 acc[4] = {0,0,0,0}, d1[4] = {0,0,0,0}, d2[4] = {0,0,0,0};
    gemm_pipe<1>(A, HDIM, W, HDIM, slice*(HDIM/4), HDIM/4,
                 rowBase, colBase, acc, d1, d2, sm.sl[slice], slice);

    __syncthreads();
    if (slice) {
        u64* d = sm.comb[slice-1][t1];
        #pragma unroll
        for (int i = 0; i < 4; i++) d[i] = acc[i];
    }
    __syncthreads();
    if (slice == 0) {
        #pragma unroll
        for (int s = 0; s < 3; s++) {
            const u64* d = sm.comb[s][t1];
            #pragma unroll
            for (int i = 0; i < 4; i++) acc[i] = add2(acc[i], d[i]);
        }
        float bb = bias[colBase + cL];
        #pragma unroll
        for (int i = 0; i < 4; i++)
            out[(size_t)(rowBase + rG*4 + i)*HDIM + colBase + cL] = red2(acc[i]) + bb;
    }
    __syncthreads();
}

// ---------------- logits + argmax for one batch row; returns argmax token ----------------
__device__ int logits_row(int b, int t,
                          const float* __restrict__ g1,
                          const float* __restrict__ outW,
                          const float* __restrict__ outb,
                          float* __restrict__ vec_out,
                          SmL& sl)
{
    const int tid = threadIdx.x;
    const int warp = tid >> 5, lane = tid & 31;

    sl.hrow[tid] = g1[(size_t)b*HDIM + tid];
    __syncthreads();

    for (int v = warp; v < VOC; v += 16) {
        const float* wrow = outW + (size_t)v*HDIM;
        float s = 0.f;
        #pragma unroll
        for (int k = lane; k < HDIM; k += 32) s = fmaf(sl.hrow[k], wrow[k], s);
        #pragma unroll
        for (int o = 16; o; o >>= 1) s += __shfl_xor_sync(0xffffffffu, s, o);
        if (!lane) {
            s += outb[v];
            sl.lg[v] = s;
            vec_out[(size_t)b*MLEN*VOC + (size_t)t*VOC + v] = s;
        }
    }
    __syncthreads();
    if (tid == 0) {
        int best = 0; float bv = sl.lg[0];
        #pragma unroll
        for (int v = 1; v < VOC; v++)
            if (sl.lg[v] > bv) { bv = sl.lg[v]; best = v; }
        sl.best = best;
    }
    __syncthreads();
    return sl.best;
}

// ---------------- attention for one batch row (512 threads); token passed by value ----------------
__device__ void attn_row(int b, int t,
                         const float* __restrict__ query,
                         const float* __restrict__ enc,
                         const float* __restrict__ emb,
                         int tk,
                         float* __restrict__ rnn_in,
                         float* __restrict__ att_out,
                         SmA& sa)
{
    const int tid = threadIdx.x;
    const int warp = tid >> 5, lane = tid & 31;

    sa.q[tid] = query[(size_t)b*HDIM + tid];
    __syncthreads();

    const float* encb = enc + (size_t)b*HDIM;
    for (int tt = warp; tt < TIN; tt += 16) {
        const float* e = encb + (size_t)tt*BH;
        float s = 0.f;
        #pragma unroll
        for (int k = lane; k < HDIM; k += 32) s = fmaf(sa.q[k], e[k], s);
        #pragma unroll
        for (int o = 16; o; o >>= 1) s += __shfl_xor_sync(0xffffffffu, s, o);
        if (!lane) sa.sc[tt] = s;
    }
    __syncthreads();

    if (tid < 256) {
        float v = sa.sc[tid];
        float m = v;
        #pragma unroll
        for (int o = 16; o; o >>= 1) m = fmaxf(m, __shfl_xor_sync(0xffffffffu, m, o));
        if (!lane) sa.red[warp] = m;
    }
    __syncthreads();
    float gm = sa.red[0];
    #pragma unroll
    for (int i = 1; i < 8; i++) gm = fmaxf(gm, sa.red[i]);
    __syncthreads();
    if (tid < 256) {
        float v = sa.sc[tid];
        float e = expf(v - gm);
        float s = e;
        #pragma unroll
        for (int o = 16; o; o >>= 1) s += __shfl_xor_sync(0xffffffffu, s, o);
        if (!lane) sa.red[8 + warp] = s;
        sa.sc[tid] = e;
    }
    __syncthreads();
    float tot = 0.f;
    #pragma unroll
    for (int i = 0; i < 8; i++) tot += sa.red[8 + i];
    float inv_tot = 1.f / tot;
    if (tid < 256) {
        float w = sa.sc[tid] * inv_tot;
        sa.sc[tid] = w;
        att_out[(size_t)b*MLEN*TIN + (size_t)t*TIN + tid] = w;
    }
    __syncthreads();

    float c = 0.f;
    #pragma unroll 4
    for (int tt = 0; tt < TIN; tt++)
        c = fmaf(sa.sc[tt], encb[(size_t)tt*BH + tid], c);
    float* rb = rnn_in + (size_t)b*1024;
    rb[512 + tid] = c;

    rb[tid] = emb[(size_t)tk*HDIM + tid];
    __syncthreads();
}

// ---------------- init kernel: zero counters + barrier state ----------------
__global__ void init_kernel()
{
    int tid = threadIdx.x;
    if (tid == 0) { g_arrive = 0; g_release = 0; }
    int* p;
    p = &cY0[0][0];  for (int i = tid; i < TIN*4;  i += 256) p[i] = 0;
    p = &cEnc[0][0]; for (int i = tid; i < TIN*4;  i += 256) p[i] = 0;
    p = &cQ[0][0];   for (int i = tid; i < MLEN*4; i += 256) p[i] = 0;
    p = &cRnn[0][0]; for (int i = tid; i < MLEN*4; i += 256) p[i] = 0;
    p = &cH0[0][0];  for (int i = tid; i < MLEN*4; i += 256) p[i] = 0;
    p = &cH1[0][0];  for (int i = tid; i < MLEN*4; i += 256) p[i] = 0;
}

// ---------------- persistent megakernel ----------------
__global__ void __launch_bounds__(NTHR, 1)
mega_kernel(const float* __restrict__ x,
            const float* __restrict__ emb,
            const float* __restrict__ eWih0, const float* __restrict__ eWhh0,
            const float* __restrict__ ebih0, const float* __restrict__ ebhh0,
            const float* __restrict__ eWih1, const float* __restrict__ eWhh1,
            const float* __restrict__ ebih1, const float* __restrict__ ebhh1,
            const float* __restrict__ dWih0, const float* __restrict__ dWhh0,
            const float* __restrict__ dbih0, const float* __restrict__ dbhh0,
            const float* __restrict__ dWih1, const float* __restrict__ dWhh1,
            const float* __restrict__ dbih1, const float* __restrict__ dbhh1,
            const float* __restrict__ qW,    const float* __restrict__ qb,
            const float* __restrict__ outW,  const float* __restrict__ outb,
            float* __restrict__ vec_out,
            float* __restrict__ hid_out,
            float* __restrict__ att_out)
{
    extern __shared__ unsigned char smraw[];
    SmAll& sm = *reinterpret_cast<SmAll*>(smraw);
    unsigned phase = 0;
    const int bid = blockIdx.x;

    // ---------- encoder: dataflow-ordered supersteps, no global syncs ----------
    // superstep s: units 0..127 = layer0 tiles for step s; 128..255 = layer1 tiles for step s-1
    for (int s = 0; s <= TIN; s++) {
        for (int u = bid; u < 256; u += NBLK) {
            int tile = u & 127;
            int rowBase = (tile >> 5) * 32;
            int colBase = (tile & 31) * 16;
            int rt = tile >> 5;
            if (u < 128) {
                if (s < TIN) {
                    const float* hprev = s ? (g_y0 + (size_t)(s-1)*BH) : nullptr;
                    waits2(s ? &cY0[s-1][rt] : nullptr, nullptr);
                    gru_tile(hprev, eWhh0, ebhh0,
                             x + (size_t)s*2, TIN*2, 2, eWih0, ebih0,
                             g_y0 + (size_t)s*BH, rowBase, colBase, sm);
                    done(&cY0[s][rt]);
                }
            } else {
                if (s >= 1) {
                    int t = s - 1;
                    const float* hprev = t ? (g_enc + (size_t)(t-1)*BH) : nullptr;
                    waits2(&cY0[t][rt], t ? &cEnc[t-1][rt] : nullptr);
                    gru_tile(hprev, eWhh1, ebhh1,
                             g_y0 + (size_t)t*BH, HDIM, HDIM, eWih1, ebih1,
                             g_enc + (size_t)t*BH, rowBase, colBase, sm);
                    done(&cEnc[t][rt]);
                }
            }
        }
    }

    // all enc outputs must be globally visible before attention reads them
    gsync(phase);

    // ---------- decoder: 512 dataflow units per step ----------
    // order: query(t) [0..127], attn+logits [128..255], gru0 [256..383], gru1 [384..511]
    for (int t = 0; t < MLEN; t++) {
        const float* h0prev = t ? (g_h0 + (size_t)(t-1)*BH) : (g_y0  + (size_t)(TIN-1)*BH);
        const float* h1prev = t ? (g_h1 + (size_t)(t-1)*BH) : (g_enc + (size_t)(TIN-1)*BH);

        for (int u = bid; u < 512; u += NBLK) {
            int ph   = u >> 7;
            int tile = u & 127;
            int rowBase = (tile >> 5) * 32;
            int colBase = (tile & 31) * 16;
            int rt = tile >> 5;

            if (ph == 0) {
                // query[t] = h1prev @ qW.T + qb
                waits2(t ? &cH1[t-1][rt] : nullptr, nullptr);
                linear_tile(h1prev, qW, qb, g_q + (size_t)t*BH, rowBase, colBase, sm);
                done(&cQ[t][rt]);
            } else if (ph == 1) {
                // logits(t-1) for row b, then attention(t) for row b
                int b = tile;
                int brt = b >> 5;
                waits2(&cQ[t][brt], t ? &cH1[t-1][brt] : nullptr);
                int tk = 0;
                if (t > 0)
                    tk = logits_row(b, t-1, g_h1 + (size_t)(t-1)*BH, outW, outb,
                                    vec_out, sm.l);
                attn_row(b, t, g_q + (size_t)t*BH, g_enc, emb, tk,
                         g_rnn + (size_t)t*B2H, att_out, sm.a);
                done(&cRnn[t][brt]);
            } else if (ph == 2) {
                waits2(&cRnn[t][rt], t ? &cH0[t-1][rt] : nullptr);
                gru_tile(h0prev, dWhh0, dbhh0,
                         g_rnn + (size_t)t*B2H, 2*HDIM, 2*HDIM, dWih0, dbih0,
                         g_h0 + (size_t)t*BH, rowBase, colBase, sm);
                done(&cH0[t][rt]);
            } else {
                waits2(&cH0[t][rt], t ? &cH1[t-1][rt] : nullptr);
                gru_tile(h1prev, dWhh1, dbhh1,
                         g_h0 + (size_t)t*BH, HDIM, HDIM, dWih1, dbih1,
                         g_h1 + (size_t)t*BH, rowBase, colBase, sm);
                done(&cH1[t][rt]);
            }
        }
    }

    // ---------- final logits for t = MLEN-1 ----------
    for (int u = bid; u < 128; u += NBLK) {
        int brt = u >> 5;
        waits2(&cH1[MLEN-1][brt], nullptr);
        logits_row(u, MLEN-1, g_h1 + (size_t)(MLEN-1)*BH, outW, outb,
                   vec_out, sm.l);
    }

    // ---------- final hidden copy ----------
    gsync(phase);
    for (int i = bid*NTHR + threadIdx.x; i < BH; i += NBLK*NTHR) {
        hid_out[i]      = g_h0[(size_t)(MLEN-1)*BH + i];
        hid_out[BH + i] = g_h1[(size_t)(MLEN-1)*BH + i];
    }
}

// ---------------- host ----------------
extern "C" void kernel_launch(void* const* d_in, const int* in_sizes, int n_in,
                              void* d_out, int out_size)
{
    const float* x     = (const float*)d_in[0];
    const float* emb   = (const float*)d_in[1];
    const float* eWih0 = (const float*)d_in[2];
    const float* eWhh0 = (const float*)d_in[3];
    const float* ebih0 = (const float*)d_in[4];
    const float* ebhh0 = (const float*)d_in[5];
    const float* eWih1 = (const float*)d_in[6];
    const float* eWhh1 = (const float*)d_in[7];
    const float* ebih1 = (const float*)d_in[8];
    const float* ebhh1 = (const float*)d_in[9];
    const float* dWih0 = (const float*)d_in[10];
    const float* dWhh0 = (const float*)d_in[11];
    const float* dbih0 = (const float*)d_in[12];
    const float* dbhh0 = (const float*)d_in[13];
    const float* dWih1 = (const float*)d_in[14];
    const float* dWhh1 = (const float*)d_in[15];
    const float* dbih1 = (const float*)d_in[16];
    const float* dbhh1 = (const float*)d_in[17];
    const float* qW    = (const float*)d_in[18];
    const float* qb    = (const float*)d_in[19];
    const float* outW  = (const float*)d_in[20];
    const float* outb  = (const float*)d_in[21];

    float* out     = (float*)d_out;
    float* vec_out = out;
    float* hid_out = out + (size_t)BSZ*MLEN*VOC;
    float* att_out = hid_out + 2*BH;

    static int smem_set = 0;
    if (!smem_set) {
        cudaFuncSetAttribute(mega_kernel,
                             cudaFuncAttributeMaxDynamicSharedMemorySize,
                             (int)sizeof(SmAll));
        smem_set = 1;
    }

    init_kernel<<<1, 256>>>();
    mega_kernel<<<NBLK, NTHR, sizeof(SmAll)>>>(x, emb,
                                eWih0, eWhh0, ebih0, ebhh0,
                                eWih1, eWhh1, ebih1, ebhh1,
                                dWih0, dWhh0, dbih0, dbhh0,
                                dWih1, dWhh1, dbih1, dbhh1,
                                qW, qb, outW, outb,
                                vec_out, hid_out, att_out);
}